// round 1
// baseline (speedup 1.0000x reference)
#include <cuda_runtime.h>
#include <cuda_bf16.h>
#include <cstdint>

#define N_IMG 64
#define CH    64
#define KOUT  64
#define H     56
#define W     56
#define HW    (H*W)

#define WLD       292                  // weight smem row stride in 32-bit words (=584 bf16)
#define WSM_WORDS (KOUT*WLD)           // 18688 words
#define ASM_WORDS (6*32*68)            // 13056 words (6 rows x 32 c-pairs x 68 cols)
#define SMEM_BYTES ((WSM_WORDS + ASM_WORDS)*4)

// Pre-quantized weights, bf16, layout [m][(r*3+s)*64 + c]
__device__ __nv_bfloat16 g_wq[KOUT*576];

__global__ void quant_w_kernel(const float* __restrict__ w,
                               const float* __restrict__ scale_w) {
    int idx = blockIdx.x*256 + threadIdx.x;
    if (idx >= KOUT*576) return;
    int m  = idx / 576;
    int t  = idx - m*576;
    int rs = t >> 6;
    int c  = t & 63;
    int r  = rs/3, s = rs - r*3;
    float sw = scale_w[0];
    float wv = w[((m*CH + c)*3 + r)*3 + s];
    int iv = (int)rintf(__fmul_rn(wv, sw));
    iv = ((iv + 128) & 255) - 128;      // two's-complement 8-bit wrap (matches bit decomposition)
    g_wq[idx] = __float2bfloat16((float)iv);
}

__global__ __launch_bounds__(256)
void convq_kernel(const float* __restrict__ x,
                  const float* __restrict__ bias,
                  const float* __restrict__ scale_a,
                  const float* __restrict__ scale_w,
                  const float* __restrict__ zero_point,
                  float* __restrict__ out) {
    extern __shared__ uint32_t smem[];
    uint32_t* Wsm = smem;                       // weights [m][k] bf16, row stride 584 elems
    uint32_t* As  = smem + WSM_WORDS;           // activations, word = (row*32 + c/2)*68 + col
    __nv_bfloat16* As16 = reinterpret_cast<__nv_bfloat16*>(As);

    const int tid  = threadIdx.x;
    const int lane = tid & 31;
    const int warp = tid >> 5;
    const int img  = blockIdx.y;
    const int q    = blockIdx.x;                // output row-quad: rows 4q..4q+3

    const float sa = scale_a[0];
    const float sw = scale_w[0];
    const float zp = zero_point[0];

    // ---- stage weights (bf16 pairs, coalesced) ----
    const uint32_t* wq32 = reinterpret_cast<const uint32_t*>(g_wq);
    #pragma unroll 4
    for (int i = tid; i < KOUT*288; i += 256) {
        int m  = i / 288;
        int p2 = i - m*288;
        Wsm[m*WLD + p2] = wq32[i];
    }

    // ---- stage + quantize activations (zero padding built in) ----
    const float* xin = x + (size_t)img*CH*HW;
    for (int i = tid; i < 6*64*68; i += 256) {
        int row = i / (64*68);                  // input row local 0..5  (global 4q-1 .. 4q+4)
        int rem = i - row*(64*68);
        int c   = rem / 68;
        int col = rem - c*68;                   // smem col = input col + 1
        int ir  = q*4 + row - 1;
        int j   = col - 1;
        float v = 0.f;
        if (ir >= 0 && ir < H && (unsigned)j < (unsigned)W) {
            float xv = xin[(c*H + ir)*W + j];
            float t  = __fadd_rn(__fmul_rn(xv, sa), -zp);   // match reference rounding (no FMA fuse)
            v = fminf(fmaxf(rintf(t), 0.f), 255.f) + zp;    // q_in + zp  (zero-point folded in)
        }
        As16[(((row<<5) + (c>>1))*68 + col)*2 + (c&1)] = __float2bfloat16(v);
    }
    __syncthreads();

    // ---- implicit GEMM: D[64 x 256pad] = W[64 x 576] * A[576 x 256pad] ----
    const int mt = warp & 3;                    // m-tile (16 output channels)
    const int nh = warp >> 2;                   // 0: out rows 0-1, 1: out rows 2-3
    const int g  = lane >> 2;
    const int p  = lane & 3;

    float d[14][4];
    #pragma unroll
    for (int i = 0; i < 14; ++i) { d[i][0]=0.f; d[i][1]=0.f; d[i][2]=0.f; d[i][3]=0.f; }

    const uint32_t* Wp = Wsm + (mt*16 + g)*WLD + p;

    #pragma unroll 1
    for (int r = 0; r < 3; ++r) {
      #pragma unroll 1
      for (int s = 0; s < 3; ++s) {
        const int rs = r*3 + s;
        #pragma unroll 1
        for (int ct = 0; ct < 4; ++ct) {        // k-tile: channels ct*16..ct*16+15
            const uint32_t* wp = Wp + rs*32 + ct*8;
            uint32_t a0 = wp[0];
            uint32_t a1 = wp[8*WLD];
            uint32_t a2 = wp[4];
            uint32_t a3 = wp[8*WLD + 4];
            // B base for this (r,s,ct): conflict-free (bank = 4*cp + col)
            const uint32_t* bb = As + (((nh*2 + r)<<5) + ct*8 + p)*68 + s + g;
            int ai = 0;
            #pragma unroll
            for (int i = 0; i < 16; ++i) {
                if ((i & 7) == 7) continue;     // padded pixel tile (cols 56-63): skip
                const uint32_t* bp = bb + (i>>3)*2176 + (i&7)*8;   // 2176 = 32*68 (one input row)
                uint32_t b0 = bp[0];
                uint32_t b1 = bp[272];           // cp + 4  (k rows 8..15)
                asm volatile(
                  "mma.sync.aligned.m16n8k16.row.col.f32.bf16.bf16.f32 "
                  "{%0,%1,%2,%3}, {%4,%5,%6,%7}, {%8,%9}, {%0,%1,%2,%3};\n"
                  : "+f"(d[ai][0]), "+f"(d[ai][1]), "+f"(d[ai][2]), "+f"(d[ai][3])
                  : "r"(a0), "r"(a1), "r"(a2), "r"(a3), "r"(b0), "r"(b1));
                ++ai;
            }
        }
      }
    }

    // ---- epilogue: scale + bias, direct float2 stores (full 32B sectors) ----
    const float inv = 1.0f / (sa*sw);
    const float blo = bias[mt*16 + g];
    const float bhi = bias[mt*16 + g + 8];
    float* ob = out + (((size_t)img*KOUT + mt*16 + g)*H + q*4)*W;
    int ai = 0;
    #pragma unroll
    for (int i = 0; i < 16; ++i) {
        if ((i & 7) == 7) continue;
        int orow = nh*2 + (i>>3);
        int ocol = (i&7)*8 + p*2;               // <= 54, always valid
        float2 v0 = make_float2(d[ai][0]*inv + blo, d[ai][1]*inv + blo);
        float2 v1 = make_float2(d[ai][2]*inv + bhi, d[ai][3]*inv + bhi);
        float* o0 = ob + orow*W + ocol;
        *reinterpret_cast<float2*>(o0)          = v0;
        *reinterpret_cast<float2*>(o0 + 8*HW)   = v1;   // output channel +8
        ++ai;
    }
}

extern "C" void kernel_launch(void* const* d_in, const int* in_sizes, int n_in,
                              void* d_out, int out_size) {
    const float* x    = (const float*)d_in[0];
    const float* wgt  = (const float*)d_in[1];
    const float* bias = (const float*)d_in[2];
    const float* sa   = (const float*)d_in[3];
    const float* sw   = (const float*)d_in[4];
    const float* zp   = (const float*)d_in[5];
    float* out = (float*)d_out;

    quant_w_kernel<<<(KOUT*576 + 255)/256, 256>>>(wgt, sw);

    cudaFuncSetAttribute(convq_kernel,
        cudaFuncAttributeMaxDynamicSharedMemorySize, SMEM_BYTES);
    dim3 grid(14, N_IMG);   // 14 row-quads x 64 images = 896 CTAs
    convq_kernel<<<grid, 256, SMEM_BYTES>>>(x, bias, sa, sw, zp, out);
}

// round 2
// speedup vs baseline: 1.3556x; 1.3556x over previous
#include <cuda_runtime.h>
#include <cuda_bf16.h>
#include <cstdint>

#define N_IMG 64
#define CH    64
#define KOUT  64
#define H     56
#define W     56
#define HW    (H*W)

#define ASM_WORDS (6*32*68)            // 13056 words (6 rows x 32 c-pairs x 68 cols)
#define SMEM_BYTES (ASM_WORDS*4)       // 52224 B

// Pre-quantized weights in MMA A-fragment layout:
// uint4 index = (mt*36 + kt)*32 + lane,  kt = rs*4 + ct
// words: a0=(g, kbase+2p..+1) a1=(g+8, same) a2=(g, kbase+8+2p..+1) a3=(g+8, same)
__device__ __nv_bfloat16 g_wq[KOUT*576];

__global__ void quant_w_kernel(const float* __restrict__ w,
                               const float* __restrict__ scale_w) {
    int idx = blockIdx.x*256 + threadIdx.x;
    if (idx >= KOUT*576) return;
    int m  = idx / 576;
    int k  = idx - m*576;
    int rs = k >> 6;
    int c  = k & 63;
    int r  = rs/3, s = rs - r*3;
    float sw = scale_w[0];
    float wv = w[((m*CH + c)*3 + r)*3 + s];
    int iv = (int)rintf(__fmul_rn(wv, sw));
    iv = ((iv + 128) & 255) - 128;      // two's-complement 8-bit wrap

    // fragment position
    int mt   = m >> 4;
    int rin  = m & 15;
    int g    = rin & 7;
    int half = rin >> 3;
    int ct   = c >> 4;
    int kc   = c & 15;
    int p    = (kc >> 1) & 3;
    int hi   = kc >> 3;
    int b    = kc & 1;
    int lane = g*4 + p;
    int word = half + 2*hi;
    int pos  = (((mt*36 + rs*4 + ct)*32 + lane)*4 + word)*2 + b;
    g_wq[pos] = __float2bfloat16((float)iv);
}

__global__ __launch_bounds__(256, 3)
void convq_kernel(const float* __restrict__ x,
                  const float* __restrict__ bias,
                  const float* __restrict__ scale_a,
                  const float* __restrict__ scale_w,
                  const float* __restrict__ zero_point,
                  float* __restrict__ out) {
    extern __shared__ uint32_t smem[];
    uint32_t* As = smem;                        // activations: word = (row*32 + c/2)*68 + col
    __nv_bfloat16* As16 = reinterpret_cast<__nv_bfloat16*>(As);

    const int tid  = threadIdx.x;
    const int lane = tid & 31;
    const int warp = tid >> 5;
    const int img  = blockIdx.y;
    const int q    = blockIdx.x;                // output row-quad: rows 4q..4q+3

    const float sa = scale_a[0];
    const float sw = scale_w[0];
    const float zp = zero_point[0];

    // ---- stage + quantize activations (only cols 0..57 are ever read) ----
    const float* xin = x + (size_t)img*CH*HW;
    #pragma unroll 2
    for (int wp = 0; wp < 48; ++wp) {
        int pair = wp*8 + warp;                 // 0..383 = 6 rows x 64 channels
        int row  = pair >> 6;
        int c    = pair & 63;
        int ir   = q*4 + row - 1;
        bool rowok = (unsigned)ir < (unsigned)H;
        const float* xr = xin + (c*H + ir)*W;
        uint32_t base = (((row<<5) + (c>>1))*68)*2 + (c&1);
        #pragma unroll
        for (int h = 0; h < 2; ++h) {
            int col = lane + h*32;
            if (col < 58) {
                int j = col - 1;
                float v = 0.f;
                if (rowok && (unsigned)j < (unsigned)W) {
                    float t = __fadd_rn(__fmul_rn(xr[j], sa), -zp);   // match ref rounding
                    v = fminf(fmaxf(rintf(t), 0.f), 255.f) + zp;      // q_in + zp (zp folded)
                }
                As16[base + col*2] = __float2bfloat16(v);
            }
        }
    }
    __syncthreads();

    // ---- implicit GEMM: D[64 x 224] = W[64 x 576] * A[576 x 224] ----
    const int mt = warp & 3;                    // m-tile (16 output channels)
    const int nh = warp >> 2;                   // 0: out rows 0-1, 1: out rows 2-3
    const int g  = lane >> 2;
    const int p  = lane & 3;

    float d[14][4];
    #pragma unroll
    for (int i = 0; i < 14; ++i) { d[i][0]=0.f; d[i][1]=0.f; d[i][2]=0.f; d[i][3]=0.f; }

    const uint4* wq4 = reinterpret_cast<const uint4*>(g_wq) + (mt*36)*32 + lane;

    #pragma unroll 1
    for (int r = 0; r < 3; ++r) {
      #pragma unroll 1
      for (int s = 0; s < 3; ++s) {
        const int rs = r*3 + s;
        #pragma unroll
        for (int ct = 0; ct < 4; ++ct) {        // k-tile: channels ct*16..ct*16+15
            uint4 a = wq4[(rs*4 + ct)*32];      // LDG.128, L1-resident
            // B base for this (r,s,ct): conflict-free (bank = 4*cp + col mod 32)
            const uint32_t* bb = As + (((nh*2 + r)<<5) + ct*8 + p)*68 + s + g;
            int ai = 0;
            #pragma unroll
            for (int i = 0; i < 16; ++i) {
                if ((i & 7) == 7) continue;     // padded pixel tile (cols 56-63): skip
                const uint32_t* bp = bb + (i>>3)*2176 + (i&7)*8;   // 2176 = 32*68
                uint32_t b0 = bp[0];
                uint32_t b1 = bp[272];          // cp + 4 (k rows 8..15)
                asm volatile(
                  "mma.sync.aligned.m16n8k16.row.col.f32.bf16.bf16.f32 "
                  "{%0,%1,%2,%3}, {%4,%5,%6,%7}, {%8,%9}, {%0,%1,%2,%3};\n"
                  : "+f"(d[ai][0]), "+f"(d[ai][1]), "+f"(d[ai][2]), "+f"(d[ai][3])
                  : "r"(a.x), "r"(a.y), "r"(a.z), "r"(a.w), "r"(b0), "r"(b1));
                ++ai;
            }
        }
      }
    }

    // ---- epilogue: scale + bias, direct float2 stores ----
    const float inv = 1.0f / (sa*sw);
    const float blo = bias[mt*16 + g];
    const float bhi = bias[mt*16 + g + 8];
    float* ob = out + (((size_t)img*KOUT + mt*16 + g)*H + q*4)*W;
    int ai = 0;
    #pragma unroll
    for (int i = 0; i < 16; ++i) {
        if ((i & 7) == 7) continue;
        int orow = nh*2 + (i>>3);
        int ocol = (i&7)*8 + p*2;               // <= 54, always valid
        float2 v0 = make_float2(d[ai][0]*inv + blo, d[ai][1]*inv + blo);
        float2 v1 = make_float2(d[ai][2]*inv + bhi, d[ai][3]*inv + bhi);
        float* o0 = ob + orow*W + ocol;
        *reinterpret_cast<float2*>(o0)          = v0;
        *reinterpret_cast<float2*>(o0 + 8*HW)   = v1;   // output channel +8
        ++ai;
    }
}

extern "C" void kernel_launch(void* const* d_in, const int* in_sizes, int n_in,
                              void* d_out, int out_size) {
    const float* x    = (const float*)d_in[0];
    const float* wgt  = (const float*)d_in[1];
    const float* bias = (const float*)d_in[2];
    const float* sa   = (const float*)d_in[3];
    const float* sw   = (const float*)d_in[4];
    const float* zp   = (const float*)d_in[5];
    float* out = (float*)d_out;

    quant_w_kernel<<<(KOUT*576 + 255)/256, 256>>>(wgt, sw);

    cudaFuncSetAttribute(convq_kernel,
        cudaFuncAttributeMaxDynamicSharedMemorySize, SMEM_BYTES);
    dim3 grid(14, N_IMG);   // 14 row-quads x 64 images = 896 CTAs
    convq_kernel<<<grid, 256, SMEM_BYTES>>>(x, bias, sa, sw, zp, out);
}

// round 3
// speedup vs baseline: 1.5064x; 1.1113x over previous
#include <cuda_runtime.h>
#include <cuda_bf16.h>
#include <cstdint>

#define N_IMG 64
#define CH    64
#define KOUT  64
#define H     56
#define W     56
#define HW    (H*W)

#define ALD   72                       // activation cp-row stride in words (conflict-free: 72 mod 32 = 8)
#define AROW  (32*ALD)                 // words per input row = 2304
#define ASM_WORDS (6*AROW)             // 13824 words
#define SMEM_BYTES (ASM_WORDS*4)       // 55296 B

// Pre-quantized weights in MMA A-fragment layout:
// uint4 index = (mt*36 + kt)*32 + lane,  kt = rs*4 + ct
__device__ __nv_bfloat16 g_wq[KOUT*576];

__global__ void quant_w_kernel(const float* __restrict__ w,
                               const float* __restrict__ scale_w) {
    int idx = blockIdx.x*256 + threadIdx.x;
    if (idx >= KOUT*576) return;
    int m  = idx / 576;
    int k  = idx - m*576;
    int rs = k >> 6;
    int c  = k & 63;
    int r  = rs/3, s = rs - r*3;
    float sw = scale_w[0];
    float wv = w[((m*CH + c)*3 + r)*3 + s];
    int iv = (int)rintf(__fmul_rn(wv, sw));
    iv = ((iv + 128) & 255) - 128;      // two's-complement 8-bit wrap

    // fragment position
    int mt   = m >> 4;
    int rin  = m & 15;
    int g    = rin & 7;
    int half = rin >> 3;
    int ct   = c >> 4;
    int kc   = c & 15;
    int p    = (kc >> 1) & 3;
    int hi   = kc >> 3;
    int b    = kc & 1;
    int lane = g*4 + p;
    int word = half + 2*hi;
    int pos  = (((mt*36 + rs*4 + ct)*32 + lane)*4 + word)*2 + b;
    g_wq[pos] = __float2bfloat16((float)iv);
}

__global__ __launch_bounds__(256, 3)
void convq_kernel(const float* __restrict__ x,
                  const float* __restrict__ bias,
                  const float* __restrict__ scale_a,
                  const float* __restrict__ scale_w,
                  const float* __restrict__ zero_point,
                  float* __restrict__ out) {
    extern __shared__ uint32_t smem[];
    uint32_t* As = smem;                        // activations: word = (row*32 + c/2)*72 + col
    __nv_bfloat16* As16 = reinterpret_cast<__nv_bfloat16*>(As);

    const int tid  = threadIdx.x;
    const int lane = tid & 31;
    const int warp = tid >> 5;
    const int img  = blockIdx.y;
    const int q    = blockIdx.x;                // output row-quad: rows 4q..4q+3

    const float sa = scale_a[0];
    const float sw = scale_w[0];
    const float zp = zero_point[0];

    // ---- stage + quantize activations (only cols 0..57 are ever read) ----
    const float* xin = x + (size_t)img*CH*HW;
    #pragma unroll 2
    for (int wp = 0; wp < 48; ++wp) {
        int pair = wp*8 + warp;                 // 0..383 = 6 rows x 64 channels
        int row  = pair >> 6;
        int c    = pair & 63;
        int ir   = q*4 + row - 1;
        bool rowok = (unsigned)ir < (unsigned)H;
        const float* xr = xin + (c*H + ir)*W;
        uint32_t base = (((row<<5) + (c>>1))*ALD)*2 + (c&1);
        #pragma unroll
        for (int h = 0; h < 2; ++h) {
            int col = lane + h*32;
            if (col < 58) {
                int j = col - 1;
                float v = 0.f;
                if (rowok && (unsigned)j < (unsigned)W) {
                    float t = __fadd_rn(__fmul_rn(xr[j], sa), -zp);   // match ref rounding
                    v = fminf(fmaxf(rintf(t), 0.f), 255.f) + zp;      // q_in + zp (zp folded)
                }
                As16[base + col*2] = __float2bfloat16(v);
            }
        }
    }
    __syncthreads();

    // ---- implicit GEMM: D[64 x 224] = W[64 x 576] * A[576 x 224] ----
    const int mt = warp & 3;                    // m-tile (16 output channels)
    const int nh = warp >> 2;                   // 0: out rows 0-1, 1: out rows 2-3
    const int g  = lane >> 2;
    const int p  = lane & 3;

    float d[14][4];
    #pragma unroll
    for (int i = 0; i < 14; ++i) { d[i][0]=0.f; d[i][1]=0.f; d[i][2]=0.f; d[i][3]=0.f; }

    const uint4* wq4 = reinterpret_cast<const uint4*>(g_wq) + (mt*36)*32 + lane;

    #pragma unroll 1
    for (int r = 0; r < 3; ++r) {
      #pragma unroll 1
      for (int s = 0; s < 3; ++s) {
        const int rs = r*3 + s;
        #pragma unroll
        for (int ct = 0; ct < 4; ++ct) {        // k-tile: channels ct*16..ct*16+15
            uint4 a = wq4[(rs*4 + ct)*32];      // LDG.128, L1-resident
            // B base: bank = (8p + g + s + const) mod 32 -> bijective, conflict-free
            const uint32_t* bb = As + (((nh*2 + r)<<5) + ct*8 + p)*ALD + s + g;
            int ai = 0;
            #pragma unroll
            for (int i = 0; i < 16; ++i) {
                if ((i & 7) == 7) continue;     // padded pixel tile (cols 56-63): skip
                const uint32_t* bp = bb + (i>>3)*AROW + (i&7)*8;
                uint32_t b0 = bp[0];
                uint32_t b1 = bp[4*ALD];        // cp + 4 (k rows 8..15), +288 ≡ 0 mod 32
                asm volatile(
                  "mma.sync.aligned.m16n8k16.row.col.f32.bf16.bf16.f32 "
                  "{%0,%1,%2,%3}, {%4,%5,%6,%7}, {%8,%9}, {%0,%1,%2,%3};\n"
                  : "+f"(d[ai][0]), "+f"(d[ai][1]), "+f"(d[ai][2]), "+f"(d[ai][3])
                  : "r"(a.x), "r"(a.y), "r"(a.z), "r"(a.w), "r"(b0), "r"(b1));
                ++ai;
            }
        }
      }
    }

    // ---- epilogue: scale + bias, direct float2 stores ----
    const float inv = 1.0f / (sa*sw);
    const float blo = bias[mt*16 + g];
    const float bhi = bias[mt*16 + g + 8];
    float* ob = out + (((size_t)img*KOUT + mt*16 + g)*H + q*4)*W;
    int ai = 0;
    #pragma unroll
    for (int i = 0; i < 16; ++i) {
        if ((i & 7) == 7) continue;
        int orow = nh*2 + (i>>3);
        int ocol = (i&7)*8 + p*2;               // <= 54, always valid
        float2 v0 = make_float2(d[ai][0]*inv + blo, d[ai][1]*inv + blo);
        float2 v1 = make_float2(d[ai][2]*inv + bhi, d[ai][3]*inv + bhi);
        float* o0 = ob + orow*W + ocol;
        *reinterpret_cast<float2*>(o0)          = v0;
        *reinterpret_cast<float2*>(o0 + 8*HW)   = v1;   // output channel +8
        ++ai;
    }
}

extern "C" void kernel_launch(void* const* d_in, const int* in_sizes, int n_in,
                              void* d_out, int out_size) {
    const float* x    = (const float*)d_in[0];
    const float* wgt  = (const float*)d_in[1];
    const float* bias = (const float*)d_in[2];
    const float* sa   = (const float*)d_in[3];
    const float* sw   = (const float*)d_in[4];
    const float* zp   = (const float*)d_in[5];
    float* out = (float*)d_out;

    quant_w_kernel<<<(KOUT*576 + 255)/256, 256>>>(wgt, sw);

    cudaFuncSetAttribute(convq_kernel,
        cudaFuncAttributeMaxDynamicSharedMemorySize, SMEM_BYTES);
    dim3 grid(14, N_IMG);   // 14 row-quads x 64 images = 896 CTAs
    convq_kernel<<<grid, 256, SMEM_BYTES>>>(x, bias, sa, sw, zp, out);
}

// round 4
// speedup vs baseline: 1.5267x; 1.0135x over previous
#include <cuda_runtime.h>
#include <cuda_bf16.h>
#include <cstdint>

#define N_IMG 64
#define CH    64
#define KOUT  64
#define H     56
#define W     56
#define HW    (H*W)

#define ALD   72                       // activation cp-row stride in words (conflict-free: 72 mod 32 = 8)
#define AROW  (32*ALD)                 // words per input row = 2304
#define ASM_WORDS (6*AROW)             // 13824 words
#define SMEM_BYTES (ASM_WORDS*4)       // 55296 B

// Pre-quantized weights in MMA A-fragment layout:
// uint4 index = (mt*36 + kt)*32 + lane,  kt = rs*4 + ct
__device__ __nv_bfloat16 g_wq[KOUT*576];

__global__ void quant_w_kernel(const float* __restrict__ w,
                               const float* __restrict__ scale_w) {
    int idx = blockIdx.x*256 + threadIdx.x;
    if (idx >= KOUT*576) return;
    int m  = idx / 576;
    int k  = idx - m*576;
    int rs = k >> 6;
    int c  = k & 63;
    int r  = rs/3, s = rs - r*3;
    float sw = scale_w[0];
    float wv = w[((m*CH + c)*3 + r)*3 + s];
    int iv = (int)rintf(__fmul_rn(wv, sw));
    iv = ((iv + 128) & 255) - 128;      // two's-complement 8-bit wrap

    // fragment position
    int mt   = m >> 4;
    int rin  = m & 15;
    int g    = rin & 7;
    int half = rin >> 3;
    int ct   = c >> 4;
    int kc   = c & 15;
    int p    = (kc >> 1) & 3;
    int hi   = kc >> 3;
    int b    = kc & 1;
    int lane = g*4 + p;
    int word = half + 2*hi;
    int pos  = (((mt*36 + rs*4 + ct)*32 + lane)*4 + word)*2 + b;
    g_wq[pos] = __float2bfloat16((float)iv);
}

__global__ __launch_bounds__(256, 3)
void convq_kernel(const float* __restrict__ x,
                  const float* __restrict__ bias,
                  const float* __restrict__ scale_a,
                  const float* __restrict__ scale_w,
                  const float* __restrict__ zero_point,
                  float* __restrict__ out) {
    extern __shared__ uint32_t smem[];
    uint32_t* As = smem;                        // activations: word = (row*32 + c/2)*72 + col
    __nv_bfloat16* As16 = reinterpret_cast<__nv_bfloat16*>(As);

    const int tid  = threadIdx.x;
    const int lane = tid & 31;
    const int warp = tid >> 5;
    const int img  = blockIdx.y;
    const int q    = blockIdx.x;                // output row-quad: rows 4q..4q+3

    const float sa = scale_a[0];
    const float sw = scale_w[0];
    const float zp = zero_point[0];

    // ---- stage + quantize activations (only cols 0..57 are ever read) ----
    const float* xin = x + (size_t)img*CH*HW;
    #pragma unroll 2
    for (int wp = 0; wp < 48; ++wp) {
        int pair = wp*8 + warp;                 // 0..383 = 6 rows x 64 channels
        int row  = pair >> 6;
        int c    = pair & 63;
        int ir   = q*4 + row - 1;
        bool rowok = (unsigned)ir < (unsigned)H;
        const float* xr = xin + (c*H + ir)*W;
        uint32_t base = (((row<<5) + (c>>1))*ALD)*2 + (c&1);
        #pragma unroll
        for (int h = 0; h < 2; ++h) {
            int col = lane + h*32;
            if (col < 58) {
                int j = col - 1;
                float v = 0.f;
                if (rowok && (unsigned)j < (unsigned)W) {
                    float t = __fadd_rn(__fmul_rn(xr[j], sa), -zp);   // match ref rounding
                    v = fminf(fmaxf(rintf(t), 0.f), 255.f) + zp;      // q_in + zp (zp folded)
                }
                As16[base + col*2] = __float2bfloat16(v);
            }
        }
    }
    __syncthreads();

    // ---- implicit GEMM: D[64 x 224] = W[64 x 576] * A[576 x 224] ----
    const int mt = warp & 3;                    // m-tile (16 output channels)
    const int nh = warp >> 2;                   // 0: out rows 0-1, 1: out rows 2-3
    const int g  = lane >> 2;
    const int p  = lane & 3;

    float d[14][4];
    #pragma unroll
    for (int i = 0; i < 14; ++i) { d[i][0]=0.f; d[i][1]=0.f; d[i][2]=0.f; d[i][3]=0.f; }

    const uint4* wq4 = reinterpret_cast<const uint4*>(g_wq) + (mt*36)*32 + lane;

    #pragma unroll 1
    for (int r = 0; r < 3; ++r) {
      #pragma unroll 1
      for (int s = 0; s < 3; ++s) {
        const int rs = r*3 + s;
        #pragma unroll
        for (int ct = 0; ct < 4; ++ct) {        // k-tile: channels ct*16..ct*16+15
            uint4 a = wq4[(rs*4 + ct)*32];      // LDG.128, L1-resident
            // B base: bank = (8p + g + s + const) mod 32 -> bijective, conflict-free
            const uint32_t* bb = As + (((nh*2 + r)<<5) + ct*8 + p)*ALD + s + g;
            int ai = 0;
            #pragma unroll
            for (int i = 0; i < 16; ++i) {
                if ((i & 7) == 7) continue;     // padded pixel tile (cols 56-63): skip
                const uint32_t* bp = bb + (i>>3)*AROW + (i&7)*8;
                uint32_t b0 = bp[0];
                uint32_t b1 = bp[4*ALD];        // cp + 4 (k rows 8..15), +288 ≡ 0 mod 32
                asm volatile(
                  "mma.sync.aligned.m16n8k16.row.col.f32.bf16.bf16.f32 "
                  "{%0,%1,%2,%3}, {%4,%5,%6,%7}, {%8,%9}, {%0,%1,%2,%3};\n"
                  : "+f"(d[ai][0]), "+f"(d[ai][1]), "+f"(d[ai][2]), "+f"(d[ai][3])
                  : "r"(a.x), "r"(a.y), "r"(a.z), "r"(a.w), "r"(b0), "r"(b1));
                ++ai;
            }
        }
      }
    }

    // ---- epilogue: scale + bias, direct float2 stores ----
    const float inv = 1.0f / (sa*sw);
    const float blo = bias[mt*16 + g];
    const float bhi = bias[mt*16 + g + 8];
    float* ob = out + (((size_t)img*KOUT + mt*16 + g)*H + q*4)*W;
    int ai = 0;
    #pragma unroll
    for (int i = 0; i < 16; ++i) {
        if ((i & 7) == 7) continue;
        int orow = nh*2 + (i>>3);
        int ocol = (i&7)*8 + p*2;               // <= 54, always valid
        float2 v0 = make_float2(d[ai][0]*inv + blo, d[ai][1]*inv + blo);
        float2 v1 = make_float2(d[ai][2]*inv + bhi, d[ai][3]*inv + bhi);
        float* o0 = ob + orow*W + ocol;
        *reinterpret_cast<float2*>(o0)          = v0;
        *reinterpret_cast<float2*>(o0 + 8*HW)   = v1;   // output channel +8
        ++ai;
    }
}

extern "C" void kernel_launch(void* const* d_in, const int* in_sizes, int n_in,
                              void* d_out, int out_size) {
    const float* x    = (const float*)d_in[0];
    const float* wgt  = (const float*)d_in[1];
    const float* bias = (const float*)d_in[2];
    const float* sa   = (const float*)d_in[3];
    const float* sw   = (const float*)d_in[4];
    const float* zp   = (const float*)d_in[5];
    float* out = (float*)d_out;

    quant_w_kernel<<<(KOUT*576 + 255)/256, 256>>>(wgt, sw);

    cudaFuncSetAttribute(convq_kernel,
        cudaFuncAttributeMaxDynamicSharedMemorySize, SMEM_BYTES);
    dim3 grid(14, N_IMG);   // 14 row-quads x 64 images = 896 CTAs
    convq_kernel<<<grid, 256, SMEM_BYTES>>>(x, bias, sa, sw, zp, out);
}

// round 5
// speedup vs baseline: 1.5302x; 1.0023x over previous
#include <cuda_runtime.h>
#include <cstdint>

#define N_IMG 64
#define CH    64
#define KOUT  64
#define H     56
#define W     56
#define HW    (H*W)

// Packed quantized activations (int8, 4 channels/word, hi-interleaved):
// byte(img, pq, row, col, hi, e) at ((((img*8+pq)*56+row)*64+col)*2+hi)*4+e
// channel c = (pq>>2)*32 + hi*16 + (pq&3)*4 + e ; col 0 and 57..63 are zero pad
__device__ uint4 g_qa4[(N_IMG*8*56*64*2)/4];           // 14.7 MB
// Weights int8 packed in m16n8k32 A-fragment layout:
// uint4 index = (mt*18 + rs*2 + ct2)*32 + lane
__device__ uint4 g_wq4[(KOUT*576)/16];                  // 36 KB

__global__ void quant_w_kernel(const float* __restrict__ w,
                               const float* __restrict__ scale_w) {
    int idx = blockIdx.x*256 + threadIdx.x;
    if (idx >= KOUT*576) return;
    int m  = idx / 576;
    int k  = idx - m*576;
    int rs = k >> 6;
    int c  = k & 63;
    int r  = rs/3, s = rs - r*3;
    float sw = scale_w[0];
    float wv = w[((m*CH + c)*3 + r)*3 + s];
    int iv = (int)rintf(__fmul_rn(wv, sw));
    iv = ((iv + 128) & 255) - 128;              // two's-complement s8 wrap

    int mt   = m >> 4;
    int rin  = m & 15;
    int g    = rin & 7;
    int half = rin >> 3;
    int ct2  = c >> 5;
    int kk   = c & 31;
    int e    = kk & 3;
    int p    = (kk >> 2) & 3;
    int hi   = kk >> 4;
    int lane = g*4 + p;
    int word = half + 2*hi;                     // a0,a1,a2,a3
    size_t pos = ((size_t)((mt*18 + rs*2 + ct2)*32 + lane)*4 + word)*4 + e;
    reinterpret_cast<int8_t*>(g_wq4)[pos] = (int8_t)iv;
}

// Quantize + pack activations: one thread per packed word (4 channels @ one pixel).
__global__ __launch_bounds__(256)
void quant_a_kernel(const float* __restrict__ x,
                    const float* __restrict__ scale_a,
                    const float* __restrict__ zero_point) {
    const int t   = threadIdx.x;
    const int col = t & 63;
    const int hi  = (t >> 6) & 1;
    const int row = blockIdx.x*2 + (t >> 7);    // blockIdx.x in 0..27
    const int pq  = blockIdx.y;                 // 0..7
    const int img = blockIdx.z;

    const float sa = scale_a[0];
    const float zp = zero_point[0];

    const int c0 = (pq >> 2)*32 + hi*16 + (pq & 3)*4;
    const int j  = col - 1;
    uint32_t packed = 0;
    if ((unsigned)j < (unsigned)W) {
        const float* xb = x + (size_t)(img*CH + c0)*HW + row*W + j;
        #pragma unroll
        for (int e = 0; e < 4; ++e) {
            float xv = xb[e*HW];
            float tq = __fadd_rn(__fmul_rn(xv, sa), -zp);   // match ref rounding
            float v  = fminf(fmaxf(rintf(tq), 0.f), 255.f) + zp;  // q_in + zp
            int ib   = (int)v;                  // in [-128,127]
            packed  |= (uint32_t)(ib & 255) << (e*8);
        }
    }
    reinterpret_cast<uint32_t*>(g_qa4)[
        (((size_t)(img*8 + pq)*56 + row)*64 + col)*2 + hi] = packed;
}

#define ALD8  76                       // B row stride in 8-byte units (conflict-free)
#define SMEM_WORDS (48*152)            // 6 rows x 8 pq x 152 words = 7296
#define SMEM_BYTES (SMEM_WORDS*4)      // 29184 B

__global__ __launch_bounds__(256, 3)
void convq_kernel(const float* __restrict__ bias,
                  const float* __restrict__ scale_a,
                  const float* __restrict__ scale_w,
                  float* __restrict__ out) {
    extern __shared__ uint32_t smem[];

    const int tid  = threadIdx.x;
    const int lane = tid & 31;
    const int warp = tid >> 5;
    const int img  = blockIdx.y;
    const int q    = blockIdx.x;                // output rows 4q..4q+3

    // ---- stage packed activations via cp.async (zfill for boundary rows) ----
    {
        uint32_t sbase;
        asm("{ .reg .u64 t; cvta.to.shared.u64 t, %1; cvt.u32.u64 %0, t; }"
            : "=r"(sbase) : "l"(smem));
        #pragma unroll
        for (int k = 0; k < 6; ++k) {
            int ch  = tid + k*256;              // 0..1535
            int cc  = ch & 31;                  // 16B chunk within (row,pq)
            int pq  = (ch >> 5) & 7;
            int row = ch >> 8;                  // 0..5
            int ir  = q*4 + row - 1;
            int sz  = ((unsigned)ir < (unsigned)H) ? 16 : 0;
            int irc = min(max(ir, 0), H-1);
            const char* src = reinterpret_cast<const char*>(g_qa4)
                + ((((size_t)(img*8 + pq)*56 + irc)*64)*2 + cc*4)*4;
            uint32_t dst = sbase + (((row*8 + pq)*152) + cc*4)*4;
            asm volatile("cp.async.cg.shared.global [%0], [%1], 16, %2;\n"
                         :: "r"(dst), "l"(src), "r"(sz) : "memory");
        }
        asm volatile("cp.async.commit_group;\n" ::: "memory");
        asm volatile("cp.async.wait_group 0;\n" ::: "memory");
    }
    __syncthreads();

    // ---- implicit GEMM (int8): D[64 x 224] = W[64 x 576] * A[576 x 224] ----
    const int mt = warp & 3;                    // 16 output channels
    const int nh = warp >> 2;                   // output row pair
    const int g  = lane >> 2;
    const int p  = lane & 3;

    int d[14][4];
    #pragma unroll
    for (int i = 0; i < 14; ++i) { d[i][0]=0; d[i][1]=0; d[i][2]=0; d[i][3]=0; }

    const uint4* wq = g_wq4 + (size_t)(mt*18)*32 + lane;
    const uint2* As8 = reinterpret_cast<const uint2*>(smem);

    #pragma unroll 1
    for (int r = 0; r < 3; ++r) {
      #pragma unroll 1
      for (int s = 0; s < 3; ++s) {
        #pragma unroll
        for (int ct2 = 0; ct2 < 2; ++ct2) {
            uint4 a = wq[(((r*3+s)*2) + ct2)*32];       // LDG.128, L1-resident
            // 8B index: bank-bijective (152p + 2g) mod 32 per half-warp
            const uint2* bb = As8 + ((nh*2 + r)*8 + ct2*4 + p)*ALD8 + s + g;
            int ai = 0;
            #pragma unroll
            for (int i = 0; i < 16; ++i) {
                if ((i & 7) == 7) continue;     // padded pixel tile: skip
                const uint2* bp = bb + (i>>3)*(8*ALD8) + (i&7)*8;
                uint2 b = bp[0];                // LDS.64: b0,b1
                asm volatile(
                  "mma.sync.aligned.m16n8k32.row.col.s32.s8.s8.s32 "
                  "{%0,%1,%2,%3}, {%4,%5,%6,%7}, {%8,%9}, {%0,%1,%2,%3};\n"
                  : "+r"(d[ai][0]), "+r"(d[ai][1]), "+r"(d[ai][2]), "+r"(d[ai][3])
                  : "r"(a.x), "r"(a.y), "r"(a.z), "r"(a.w), "r"(b.x), "r"(b.y));
                ++ai;
            }
        }
      }
    }

    // ---- epilogue: int -> float, scale + bias, float2 stores ----
    const float inv = 1.0f / (scale_a[0]*scale_w[0]);
    const float blo = bias[mt*16 + g];
    const float bhi = bias[mt*16 + g + 8];
    float* ob = out + (((size_t)img*KOUT + mt*16 + g)*H + q*4)*W;
    int ai = 0;
    #pragma unroll
    for (int i = 0; i < 16; ++i) {
        if ((i & 7) == 7) continue;
        int orow = nh*2 + (i>>3);
        int ocol = (i&7)*8 + p*2;
        float2 v0 = make_float2(__int2float_rn(d[ai][0])*inv + blo,
                                __int2float_rn(d[ai][1])*inv + blo);
        float2 v1 = make_float2(__int2float_rn(d[ai][2])*inv + bhi,
                                __int2float_rn(d[ai][3])*inv + bhi);
        float* o0 = ob + orow*W + ocol;
        *reinterpret_cast<float2*>(o0)        = v0;
        *reinterpret_cast<float2*>(o0 + 8*HW) = v1;     // output channel +8
        ++ai;
    }
}

extern "C" void kernel_launch(void* const* d_in, const int* in_sizes, int n_in,
                              void* d_out, int out_size) {
    const float* x    = (const float*)d_in[0];
    const float* wgt  = (const float*)d_in[1];
    const float* bias = (const float*)d_in[2];
    const float* sa   = (const float*)d_in[3];
    const float* sw   = (const float*)d_in[4];
    const float* zp   = (const float*)d_in[5];
    float* out = (float*)d_out;

    quant_w_kernel<<<(KOUT*576 + 255)/256, 256>>>(wgt, sw);

    dim3 gq(28, 8, N_IMG);
    quant_a_kernel<<<gq, 256>>>(x, sa, zp);

    cudaFuncSetAttribute(convq_kernel,
        cudaFuncAttributeMaxDynamicSharedMemorySize, SMEM_BYTES);
    dim3 grid(14, N_IMG);
    convq_kernel<<<grid, 256, SMEM_BYTES>>>(bias, sa, sw, out);
}

// round 6
// speedup vs baseline: 1.5613x; 1.0203x over previous
#include <cuda_runtime.h>
#include <cstdint>

#define N_IMG 64
#define CH    64
#define KOUT  64
#define H     56
#define W     56
#define HW    (H*W)

// Packed quantized activations (int8, 4 channels/word, hi-interleaved):
// byte(img, pq, row, col, hi, e) at ((((img*8+pq)*56+row)*64+col)*2+hi)*4+e
// channel c = (pq>>2)*32 + hi*16 + (pq&3)*4 + e ; col 0 and 57..63 are zero pad
__device__ uint4 g_qa4[(N_IMG*8*56*64*2)/4];           // 14.7 MB
// Weights int8 packed in m16n8k32 A-fragment layout:
// uint4 index = (mt*18 + rs*2 + ct2)*32 + lane
__device__ uint4 g_wq4[(KOUT*576)/16];                  // 36 KB

__global__ void quant_w_kernel(const float* __restrict__ w,
                               const float* __restrict__ scale_w) {
    int idx = blockIdx.x*256 + threadIdx.x;
    if (idx >= KOUT*576) return;
    int m  = idx / 576;
    int k  = idx - m*576;
    int rs = k >> 6;
    int c  = k & 63;
    int r  = rs/3, s = rs - r*3;
    float sw = scale_w[0];
    float wv = w[((m*CH + c)*3 + r)*3 + s];
    int iv = (int)rintf(__fmul_rn(wv, sw));
    iv = ((iv + 128) & 255) - 128;              // two's-complement s8 wrap

    int mt   = m >> 4;
    int rin  = m & 15;
    int g    = rin & 7;
    int half = rin >> 3;
    int ct2  = c >> 5;
    int kk   = c & 31;
    int e    = kk & 3;
    int p    = (kk >> 2) & 3;
    int hi   = kk >> 4;
    int lane = g*4 + p;
    int word = half + 2*hi;                     // a0,a1,a2,a3
    size_t pos = ((size_t)((mt*18 + rs*2 + ct2)*32 + lane)*4 + word)*4 + e;
    reinterpret_cast<int8_t*>(g_wq4)[pos] = (int8_t)iv;
}

// Quantize + pack activations: one thread per packed word (4 channels @ one pixel).
__global__ __launch_bounds__(256)
void quant_a_kernel(const float* __restrict__ x,
                    const float* __restrict__ scale_a,
                    const float* __restrict__ zero_point) {
    const int t   = threadIdx.x;
    const int col = t & 63;
    const int hi  = (t >> 6) & 1;
    const int row = blockIdx.x*2 + (t >> 7);    // blockIdx.x in 0..27
    const int pq  = blockIdx.y;                 // 0..7
    const int img = blockIdx.z;

    const float sa = scale_a[0];
    const float zp = zero_point[0];

    const int c0 = (pq >> 2)*32 + hi*16 + (pq & 3)*4;
    const int j  = col - 1;
    uint32_t packed = 0;
    if ((unsigned)j < (unsigned)W) {
        const float* xb = x + (size_t)(img*CH + c0)*HW + row*W + j;
        #pragma unroll
        for (int e = 0; e < 4; ++e) {
            float xv = xb[e*HW];
            float tq = __fadd_rn(__fmul_rn(xv, sa), -zp);   // match ref rounding
            float v  = fminf(fmaxf(rintf(tq), 0.f), 255.f) + zp;  // q_in + zp
            int ib   = (int)v;                  // in [-128,127]
            packed  |= (uint32_t)(ib & 255) << (e*8);
        }
    }
    reinterpret_cast<uint32_t*>(g_qa4)[
        (((size_t)(img*8 + pq)*56 + row)*64 + col)*2 + hi] = packed;
}

#define ALD8  76                       // B row stride in 8-byte units (conflict-free)
#define SMEM_WORDS (32*152)            // 4 input rows x 8 pq x 152 words = 4864
#define SMEM_BYTES (SMEM_WORDS*4)      // 19456 B

__global__ __launch_bounds__(256, 4)
void convq_kernel(const float* __restrict__ bias,
                  const float* __restrict__ scale_a,
                  const float* __restrict__ scale_w,
                  float* __restrict__ out) {
    extern __shared__ uint32_t smem[];

    const int tid  = threadIdx.x;
    const int lane = tid & 31;
    const int warp = tid >> 5;
    const int img  = blockIdx.y;
    const int q    = blockIdx.x;                // output rows 2q, 2q+1

    // ---- stage packed activations via cp.async (zfill for boundary rows) ----
    {
        uint32_t sbase;
        asm("{ .reg .u64 t; cvta.to.shared.u64 t, %1; cvt.u32.u64 %0, t; }"
            : "=r"(sbase) : "l"(smem));
        #pragma unroll
        for (int k = 0; k < 4; ++k) {
            int ch  = tid + k*256;              // 0..1023
            int cc  = ch & 31;                  // 16B chunk within (row,pq)
            int pq  = (ch >> 5) & 7;
            int row = ch >> 8;                  // input row local 0..3
            int ir  = q*2 + row - 1;
            int sz  = ((unsigned)ir < (unsigned)H) ? 16 : 0;
            int irc = min(max(ir, 0), H-1);
            const char* src = reinterpret_cast<const char*>(g_qa4)
                + ((((size_t)(img*8 + pq)*56 + irc)*64)*2 + cc*4)*4;
            uint32_t dst = sbase + (((row*8 + pq)*152) + cc*4)*4;
            asm volatile("cp.async.cg.shared.global [%0], [%1], 16, %2;\n"
                         :: "r"(dst), "l"(src), "r"(sz) : "memory");
        }
        asm volatile("cp.async.commit_group;\n" ::: "memory");
        asm volatile("cp.async.wait_group 0;\n" ::: "memory");
    }
    __syncthreads();

    // ---- implicit GEMM (int8): per warp = 16 out channels x 1 out row ----
    const int mt  = warp & 3;                   // 16 output channels
    const int nh2 = warp >> 2;                  // output row: 2q + nh2
    const int g   = lane >> 2;
    const int p   = lane & 3;

    int d[7][4];
    #pragma unroll
    for (int i = 0; i < 7; ++i) { d[i][0]=0; d[i][1]=0; d[i][2]=0; d[i][3]=0; }

    const uint4* wq = g_wq4 + (size_t)(mt*18)*32 + lane;
    const uint2* As8 = reinterpret_cast<const uint2*>(smem);

    #pragma unroll 1
    for (int r = 0; r < 3; ++r) {
      #pragma unroll
      for (int s = 0; s < 3; ++s) {
        #pragma unroll
        for (int ct2 = 0; ct2 < 2; ++ct2) {
            uint4 a = wq[(((r*3+s)*2) + ct2)*32];       // LDG.128, L1/L2-resident
            // 8B index: bank-pair (12p + g) mod 16 bijective per half-warp
            const uint2* bb = As8 + ((nh2 + r)*8 + ct2*4 + p)*ALD8 + s + g;
            #pragma unroll
            for (int i = 0; i < 7; ++i) {       // col tiles 0..6 (56 cols)
                uint2 b = bb[i*8];              // LDS.64: b0,b1
                asm volatile(
                  "mma.sync.aligned.m16n8k32.row.col.s32.s8.s8.s32 "
                  "{%0,%1,%2,%3}, {%4,%5,%6,%7}, {%8,%9}, {%0,%1,%2,%3};\n"
                  : "+r"(d[i][0]), "+r"(d[i][1]), "+r"(d[i][2]), "+r"(d[i][3])
                  : "r"(a.x), "r"(a.y), "r"(a.z), "r"(a.w), "r"(b.x), "r"(b.y));
            }
        }
      }
    }

    // ---- epilogue: int -> float, scale + bias, float2 stores ----
    const float inv = 1.0f / (scale_a[0]*scale_w[0]);
    const float blo = bias[mt*16 + g];
    const float bhi = bias[mt*16 + g + 8];
    float* ob = out + (((size_t)img*KOUT + mt*16 + g)*H + q*2 + nh2)*W;
    #pragma unroll
    for (int i = 0; i < 7; ++i) {
        int ocol = i*8 + p*2;
        float2 v0 = make_float2(__int2float_rn(d[i][0])*inv + blo,
                                __int2float_rn(d[i][1])*inv + blo);
        float2 v1 = make_float2(__int2float_rn(d[i][2])*inv + bhi,
                                __int2float_rn(d[i][3])*inv + bhi);
        float* o0 = ob + ocol;
        *reinterpret_cast<float2*>(o0)        = v0;
        *reinterpret_cast<float2*>(o0 + 8*HW) = v1;     // output channel +8
    }
}

extern "C" void kernel_launch(void* const* d_in, const int* in_sizes, int n_in,
                              void* d_out, int out_size) {
    const float* x    = (const float*)d_in[0];
    const float* wgt  = (const float*)d_in[1];
    const float* bias = (const float*)d_in[2];
    const float* sa   = (const float*)d_in[3];
    const float* sw   = (const float*)d_in[4];
    const float* zp   = (const float*)d_in[5];
    float* out = (float*)d_out;

    quant_w_kernel<<<(KOUT*576 + 255)/256, 256>>>(wgt, sw);

    dim3 gq(28, 8, N_IMG);
    quant_a_kernel<<<gq, 256>>>(x, sa, zp);

    cudaFuncSetAttribute(convq_kernel,
        cudaFuncAttributeMaxDynamicSharedMemorySize, SMEM_BYTES);
    dim3 grid(28, N_IMG);   // 28 row-pairs x 64 images = 1792 CTAs
    convq_kernel<<<grid, 256, SMEM_BYTES>>>(bias, sa, sw, out);
}